// round 16
// baseline (speedup 1.0000x reference)
#include <cuda_runtime.h>
#include <math.h>

#define BB 64
#define CIN 256
#define COUT 256
#define HH 64
#define WW 64
#define NB 8
#define HID 128
#define HWPIX 4096

#define TILE_H 16
#define CONV_THREADS 256
#define XT_ROWS 18                /* TILE_H + 2 halo */
#define XT_COLS 66                /* 64 + 2 halo */
#define XT_ELEMS (XT_ROWS * XT_COLS)   /* 1188 */
#define NLD 5
#define NPASS_PAIRS 64            /* channel-pairs per filter-smem pass */
#define FS2_ELEMS (NPASS_PAIRS * 9 * NB)  /* 4608 float2 = 36 KB */

// -------- scratch (no cudaMalloc allowed) --------
__device__ __align__(16) float g_pooled[BB * CIN];
__device__ __align__(16) float g_mix[BB * COUT * NB];
__device__ __align__(16) float g_y[(size_t)BB * NB * HWPIX];

// -------- packed f32x2 helpers (sm_103a) --------
static __device__ __forceinline__ unsigned long long pk2(float lo, float hi) {
    unsigned long long r;
    asm("mov.b64 %0, {%1, %2};" : "=l"(r) : "f"(lo), "f"(hi));
    return r;
}
static __device__ __forceinline__ void upk2(unsigned long long v, float &lo, float &hi) {
    asm("mov.b64 {%0, %1}, %2;" : "=f"(lo), "=f"(hi) : "l"(v));
}
static __device__ __forceinline__ unsigned long long fma2(
    unsigned long long a, unsigned long long b, unsigned long long c) {
    unsigned long long d;
    asm("fma.rn.f32x2 %0, %1, %2, %3;" : "=l"(d) : "l"(a), "l"(b), "l"(c));
    return d;
}
static __device__ __forceinline__ unsigned long long lds64(const float2* p) {
    unsigned long long r;
    asm("ld.shared.b64 %0, [%1];" : "=l"(r) : "l"((unsigned long long)__cvta_generic_to_shared(p)));
    return r;
}

// -------- kernel 1: zero g_pooled --------
__global__ void zero_kernel() {
    int i = blockIdx.x * blockDim.x + threadIdx.x;
    if (i < (BB * CIN) / 4) ((float4*)g_pooled)[i] = make_float4(0.f, 0.f, 0.f, 0.f);
}

// -------- kernel 2: fused 3x3 conv (8 filters) + pool, channel-pair fma2 --------
// (R11 kernel, verbatim — best measured conv: ~285us)
__global__ __launch_bounds__(CONV_THREADS, 2)
void conv_pool_kernel(const float* __restrict__ x, const float* __restrict__ bf) {
    extern __shared__ float2 smem2[];
    float2* fs2 = smem2;                    // [pl*9+tap][n] filter pairs (36 KB)
    float2* xd[2] = { smem2 + FS2_ELEMS, smem2 + FS2_ELEMS + XT_ELEMS };

    const int t  = threadIdx.x;
    const int w  = t >> 5;
    const int l  = t & 31;
    const int b  = blockIdx.x >> 2;
    const int h0 = (blockIdx.x & 3) * TILE_H;
    const int ra = 2 * w;                    // tile-local output row pair

    // per-thread staging slots for the 1188-elem tile
    int  offk[NLD], sidx[NLD];
    bool vk[NLD], pmk[NLD], ik[NLD];
#pragma unroll
    for (int k = 0; k < NLD; k++) {
        int idx = t + k * CONV_THREADS;
        vk[k] = false; pmk[k] = false; ik[k] = false; offk[k] = 0; sidx[k] = 0;
        if (idx < XT_ELEMS) {
            ik[k] = true;
            int row = idx / XT_COLS, col = idx % XT_COLS;
            sidx[k] = idx;
            int gh = h0 - 1 + row, gw = col - 1;
            if (gh >= 0 && gh < HH && gw >= 0 && gw < WW) {
                vk[k]  = true;
                offk[k] = gh * WW + gw;
                pmk[k] = (row >= 1 && row <= TILE_H && col >= 1 && col <= WW);
            }
        }
    }
    const float* xb = x + (size_t)b * CIN * HWPIX;

    // prefetch channel pair 0 (planes 0 and 1)
    float ld0[NLD], ld1[NLD];
#pragma unroll
    for (int k = 0; k < NLD; k++) {
        ld0[k] = vk[k] ? __ldg(xb + offk[k]) : 0.f;
        ld1[k] = vk[k] ? __ldg(xb + HWPIX + offk[k]) : 0.f;
    }

    unsigned long long acc[NB][4];   // [n][rowA:l, rowA:l+32, rowB:l, rowB:l+32]
#pragma unroll
    for (int n = 0; n < NB; n++)
#pragma unroll
        for (int j = 0; j < 4; j++) acc[n][j] = 0ULL;

    for (int pr = 0; pr < CIN / 2; pr++) {          // channel pairs
        const int pl = pr & (NPASS_PAIRS - 1);

        // stage filter pairs for this 64-pair pass
        if (pl == 0) {
            if (pr != 0) __syncthreads();           // readers of old fs2 done
            const int pbase = (pr >> 6) * 2 * NPASS_PAIRS;   // first channel of pass
            for (int i = t; i < FS2_ELEMS; i += CONV_THREADS) {
                int n = i / (NPASS_PAIRS * 9), rem = i % (NPASS_PAIRS * 9);
                int fpl = rem / 9, tap = rem % 9;
                int a0 = n * 2304 + (pbase + 2 * fpl) * 9 + tap;
                fs2[(fpl * 9 + tap) * NB + n] = make_float2(bf[a0], bf[a0 + 9]);
            }
        }

        // store interleaved tile + pool partials
        float2* xt = xd[pr & 1];
        float ps0 = 0.f, ps1 = 0.f;
#pragma unroll
        for (int k = 0; k < NLD; k++) {
            if (ik[k]) xt[sidx[k]] = make_float2(ld0[k], ld1[k]);
            if (pmk[k]) { ps0 += ld0[k]; ps1 += ld1[k]; }
        }
        __syncthreads();

        // pool partials (two interleaved shuffle chains, 2 atomics per warp)
#pragma unroll
        for (int o = 16; o > 0; o >>= 1) {
            ps0 += __shfl_down_sync(0xffffffffu, ps0, o);
            ps1 += __shfl_down_sync(0xffffffffu, ps1, o);
        }
        if (l == 0) {
            atomicAdd(&g_pooled[b * CIN + 2 * pr], ps0);
            atomicAdd(&g_pooled[b * CIN + 2 * pr + 1], ps1);
        }

        // prefetch next channel pair
        if (pr + 1 < CIN / 2) {
            const float* xc = xb + (size_t)(2 * pr + 2) * HWPIX;
#pragma unroll
            for (int k = 0; k < NLD; k++) {
                ld0[k] = vk[k] ? __ldg(xc + offk[k]) : 0.f;
                ld1[k] = vk[k] ? __ldg(xc + HWPIX + offk[k]) : 0.f;
            }
        }

        // compute: per dy, 12 conflict-free x LDS.64 + 24 broadcast f LDS.64 + 96 fma2
        const float2* fc = fs2 + pl * 72;
#pragma unroll
        for (int dy = 0; dy < 3; dy++) {
            const float2* rowA = xt + (ra + dy) * XT_COLS + l;
            const float2* rowB = rowA + XT_COLS;
            unsigned long long xa[3], xah[3], xbv[3], xbh[3];
#pragma unroll
            for (int dx = 0; dx < 3; dx++) {
                xa[dx]  = lds64(rowA + dx);
                xah[dx] = lds64(rowA + 32 + dx);
                xbv[dx] = lds64(rowB + dx);
                xbh[dx] = lds64(rowB + 32 + dx);
            }
#pragma unroll
            for (int dx = 0; dx < 3; dx++) {
                const float2* fp = fc + (dy * 3 + dx) * NB;
#pragma unroll
                for (int n = 0; n < NB; n++) {
                    unsigned long long f = lds64(fp + n);
                    acc[n][0] = fma2(xa[dx],  f, acc[n][0]);
                    acc[n][1] = fma2(xah[dx], f, acc[n][1]);
                    acc[n][2] = fma2(xbv[dx], f, acc[n][2]);
                    acc[n][3] = fma2(xbh[dx], f, acc[n][3]);
                }
            }
        }
    }

    // epilogue: y = lo+hi (sum of the two channel-parity partials)
    const int h = h0 + ra;
#pragma unroll
    for (int n = 0; n < NB; n++) {
        float* yb = g_y + ((size_t)(b * NB + n) * HWPIX) + h * WW;
        float lo, hi;
        upk2(acc[n][0], lo, hi); yb[l]           = lo + hi;
        upk2(acc[n][1], lo, hi); yb[l + 32]      = lo + hi;
        upk2(acc[n][2], lo, hi); yb[WW + l]      = lo + hi;
        upk2(acc[n][3], lo, hi); yb[WW + l + 32] = lo + hi;
    }
}

// -------- kernel 3: attention MLP + softmax, latency-optimized --------
// Grid: 64 b * 4 o-quarters = 256 blocks, 256 threads.
// Each block: full h (recomputed), then its 512-row slice of w2 with 4-row ILP
// in the shuffle reductions (4 independent chains pipeline the SHFL latency).
__global__ __launch_bounds__(256)
void mlp_kernel(const float* __restrict__ w1, const float* __restrict__ b1,
                const float* __restrict__ w2, const float* __restrict__ b2) {
    __shared__ float psm[CIN];
    __shared__ float hs[HID];
    __shared__ float raw[512];
    const int b = blockIdx.x >> 2, q = blockIdx.x & 3;
    const int t = threadIdx.x;
    const int w = t >> 5, l = t & 31;

    psm[t] = g_pooled[b * CIN + t] * (1.f / (float)HWPIX);
    __syncthreads();

    // h = relu(w1 @ pooled + b1): 8 warps x 16 rows, 2-row ILP
#pragma unroll
    for (int i = 0; i < 16; i += 2) {
        float s[2];
#pragma unroll
        for (int rr = 0; rr < 2; rr++) {
            int j = w * 16 + i + rr;
            float4 wa = *(const float4*)(w1 + (size_t)j * CIN + 8 * l);
            float4 wbv = *(const float4*)(w1 + (size_t)j * CIN + 8 * l + 4);
            const float4 pa = *(const float4*)(psm + 8 * l);
            const float4 pb = *(const float4*)(psm + 8 * l + 4);
            s[rr] = wa.x * pa.x + wa.y * pa.y + wa.z * pa.z + wa.w * pa.w
                  + wbv.x * pb.x + wbv.y * pb.y + wbv.z * pb.z + wbv.w * pb.w;
        }
#pragma unroll
        for (int o = 16; o > 0; o >>= 1) {
            s[0] += __shfl_xor_sync(0xffffffffu, s[0], o);
            s[1] += __shfl_xor_sync(0xffffffffu, s[1], o);
        }
        if (l == 0) {
            int j = w * 16 + i;
            hs[j]     = fmaxf(s[0] + b1[j], 0.f);
            hs[j + 1] = fmaxf(s[1] + b1[j + 1], 0.f);
        }
    }
    __syncthreads();

    // raw slice: rows [q*512, q*512+512), 8 warps x 64 rows, 4-row ILP
    const float4 hv0 = *(const float4*)(hs + 4 * l);
    const int rbase = q * 512 + w * 64;
#pragma unroll 2
    for (int i = 0; i < 64; i += 4) {
        float s[4];
#pragma unroll
        for (int rr = 0; rr < 4; rr++) {
            int row = rbase + i + rr;
            float4 wv = *(const float4*)(w2 + (size_t)row * HID + 4 * l);
            s[rr] = wv.x * hv0.x + wv.y * hv0.y + wv.z * hv0.z + wv.w * hv0.w;
        }
#pragma unroll
        for (int o = 16; o > 0; o >>= 1) {
#pragma unroll
            for (int rr = 0; rr < 4; rr++)
                s[rr] += __shfl_xor_sync(0xffffffffu, s[rr], o);
        }
        if (l == 0) {
#pragma unroll
            for (int rr = 0; rr < 4; rr++)
                raw[w * 64 + i + rr] = s[rr] + b2[rbase + i + rr];
        }
    }
    __syncthreads();

    // softmax over n for the 64 o's of this quarter (threads 0..63)
    if (t < 64) {
        float v[NB];
#pragma unroll
        for (int n = 0; n < NB; n++) v[n] = raw[t * NB + n];
        float m = v[0];
#pragma unroll
        for (int n = 1; n < NB; n++) m = fmaxf(m, v[n]);
        float e[NB], s = 0.f;
#pragma unroll
        for (int n = 0; n < NB; n++) { e[n] = expf(v[n] - m); s += e[n]; }
        float inv = 1.f / s;
        const int o = q * 64 + t;
#pragma unroll
        for (int n = 0; n < NB; n++) g_mix[(b * COUT + o) * NB + n] = e[n] * inv;
    }
}

// -------- kernel 4: out[b,o,p] = sum_n mix[b,o,n] * y[b,n,p] --------
// Grid: 64 b * 4 o-quarters * 4 pixel-chunks = 1024 CTAs, 256 threads, 4 px/thread.
__global__ __launch_bounds__(256)
void apply_kernel(float* __restrict__ out) {
    __shared__ __align__(16) float ms[64 * NB];
    const int b  = blockIdx.x >> 4;
    const int oq = (blockIdx.x >> 2) & 3;
    const int t  = threadIdx.x;
    const int p0 = (blockIdx.x & 3) * 1024 + t * 4;

    for (int i = t; i < 64 * NB; i += 256)
        ms[i] = g_mix[b * COUT * NB + oq * 64 * NB + i];
    __syncthreads();

    unsigned long long y2[NB][2];
#pragma unroll
    for (int n = 0; n < NB; n++) {
        float4 v = *(const float4*)(g_y + (size_t)(b * NB + n) * HWPIX + p0);
        y2[n][0] = pk2(v.x, v.y);
        y2[n][1] = pk2(v.z, v.w);
    }

    float* ob = out + ((size_t)b * COUT + oq * 64) * HWPIX + p0;
    for (int o = 0; o < 64; o++) {
        const float4 m0 = *(const float4*)(ms + o * NB);
        const float4 m1 = *(const float4*)(ms + o * NB + 4);
        float mv[8] = {m0.x, m0.y, m0.z, m0.w, m1.x, m1.y, m1.z, m1.w};
        unsigned long long a0 = 0ULL, a1 = 0ULL;
#pragma unroll
        for (int n = 0; n < NB; n++) {
            unsigned long long fb = pk2(mv[n], mv[n]);
            a0 = fma2(y2[n][0], fb, a0);
            a1 = fma2(y2[n][1], fb, a1);
        }
        float o0, o1, o2, o3;
        upk2(a0, o0, o1);
        upk2(a1, o2, o3);
        __stcs((float4*)(ob + (size_t)o * HWPIX), make_float4(o0, o1, o2, o3));
    }
}

extern "C" void kernel_launch(void* const* d_in, const int* in_sizes, int n_in,
                              void* d_out, int out_size) {
    const float* x  = (const float*)d_in[0];
    const float* w1 = (const float*)d_in[1];
    const float* b1 = (const float*)d_in[2];
    const float* w2 = (const float*)d_in[3];
    const float* b2 = (const float*)d_in[4];
    const float* bf = (const float*)d_in[5];
    float* out = (float*)d_out;

    const int smem_bytes = (FS2_ELEMS + 2 * XT_ELEMS) * (int)sizeof(float2);  // ~55.9 KB
    cudaFuncSetAttribute(conv_pool_kernel,
                         cudaFuncAttributeMaxDynamicSharedMemorySize, smem_bytes);

    zero_kernel<<<(BB * CIN / 4 + 255) / 256, 256>>>();
    conv_pool_kernel<<<BB * 4, CONV_THREADS, smem_bytes>>>(x, bf);
    mlp_kernel<<<BB * 4, 256>>>(w1, b1, w2, b2);
    apply_kernel<<<BB * 16, 256>>>(out);
}

// round 17
// speedup vs baseline: 1.3378x; 1.3378x over previous
#include <cuda_runtime.h>
#include <cuda_bf16.h>
#include <math.h>

#define BB 64
#define CIN 256
#define COUT 256
#define HH 64
#define WW 64
#define NB 8
#define HID 128
#define HWPIX 4096

#define NCHUNK 16              /* K chunks of 16 channels */
#define CPC 16                 /* channels per chunk */
#define ROWW 68                /* smem row width (words): data cols 2..65, zero pads */
#define C2S 680                /* per-channel-pair stride (words); 680 % 32 == 8 */
#define PLANE 5440             /* 8 c2 * 680 */

// -------- scratch (no cudaMalloc allowed) --------
__device__ __align__(16) uint4 g_afrag[NCHUNK * 9 * 32];   // per-lane A fragments
__device__ __align__(16) float g_pooled[BB * CIN];
__device__ __align__(16) float g_mix[BB * COUT * NB];
__device__ __align__(16) float g_y[(size_t)BB * NB * HWPIX];

// -------- helpers --------
static __device__ __forceinline__ unsigned pkbf(float a, float b) {
    __nv_bfloat162 h = __floats2bfloat162_rn(a, b);
    return *(unsigned*)&h;
}
static __device__ __forceinline__ void mma16816(float* d, const uint4& a,
                                                unsigned b0, unsigned b1) {
    asm volatile(
        "mma.sync.aligned.m16n8k16.row.col.f32.bf16.bf16.f32 "
        "{%0,%1,%2,%3}, {%4,%5,%6,%7}, {%8,%9}, {%0,%1,%2,%3};"
        : "+f"(d[0]), "+f"(d[1]), "+f"(d[2]), "+f"(d[3])
        : "r"(a.x), "r"(a.y), "r"(a.z), "r"(a.w), "r"(b0), "r"(b1));
}
static __device__ __forceinline__ float bfhi(float v) {
    return __bfloat162float(__float2bfloat16(v));
}
// packed f32x2 (apply kernel)
static __device__ __forceinline__ unsigned long long pk2(float lo, float hi) {
    unsigned long long r;
    asm("mov.b64 %0, {%1, %2};" : "=l"(r) : "f"(lo), "f"(hi));
    return r;
}
static __device__ __forceinline__ void upk2(unsigned long long v, float &lo, float &hi) {
    asm("mov.b64 {%0, %1}, %2;" : "=f"(lo), "=f"(hi) : "l"(v));
}
static __device__ __forceinline__ unsigned long long fma2(
    unsigned long long a, unsigned long long b, unsigned long long c) {
    unsigned long long d;
    asm("fma.rn.f32x2 %0, %1, %2, %3;" : "=l"(d) : "l"(a), "l"(b), "l"(c));
    return d;
}

// -------- kernel 0a: zero g_pooled --------
__global__ void zero_kernel() {
    int i = blockIdx.x * blockDim.x + threadIdx.x;
    if (i < BB * CIN) g_pooled[i] = 0.f;
}

// -------- kernel 0b: build A fragments (filters: hi rows 0-7, lo rows 8-15) --------
__global__ void prep_kernel(const float* __restrict__ bf) {
    int idx = blockIdx.x * blockDim.x + threadIdx.x;
    if (idx >= NCHUNK * 9 * 32) return;
    int lane = idx & 31, tap = (idx >> 5) % 9, chunk = idx / (9 * 32);
    int gid = lane >> 2, tig = lane & 3;
    unsigned w[4];
#pragma unroll
    for (int r = 0; r < 4; r++) {
        int m = gid + ((r & 1) ? 8 : 0);
        int kb = tig * 2 + ((r & 2) ? 8 : 0);
        int n = (m < 8) ? m : (m - 8);
        float f0 = bf[n * 2304 + (chunk * CPC + kb) * 9 + tap];
        float f1 = bf[n * 2304 + (chunk * CPC + kb + 1) * 9 + tap];
        float u0, u1;
        if (m < 8) { u0 = f0; u1 = f1; }
        else       { u0 = f0 - bfhi(f0); u1 = f1 - bfhi(f1); }
        w[r] = pkbf(u0, u1);
    }
    g_afrag[idx] = make_uint4(w[0], w[1], w[2], w[3]);
}

// -------- kernel 1: conv via mma.sync, SW-pipelined (reg prefetch) + pool --------
// Grid: 64 b * 8 htiles = 512 CTAs, 256 threads. Warp wid owns output row h0+wid.
__global__ __launch_bounds__(256)
void conv_pool_kernel(const float* __restrict__ x) {
    __shared__ __align__(16) unsigned bsm[2 * PLANE];

    const int t = threadIdx.x, wid = t >> 5, l = t & 31;
    const int b = blockIdx.x >> 3, ht = blockIdx.x & 7;
    const int h0 = ht * 8;
    const int gid = l >> 2, tig = l & 3;

    // zero smem once (pads stay zero; data cols rewritten per chunk)
    for (int i = t; i < 2 * PLANE; i += 256) bsm[i] = 0u;

    float acc[8][4];
#pragma unroll
    for (int g = 0; g < 8; g++)
#pragma unroll
        for (int j = 0; j < 4; j++) acc[g][j] = 0.f;

    const float* xb = x + (size_t)b * CIN * HWPIX;

    // prefetch chunk 0 into registers
    float4 pf[10];
#pragma unroll
    for (int uu = 0; uu < 10; uu++) {
        int u = wid * 10 + uu;
        int ru = u >> 3, c2 = u & 7;
        int h = h0 - 1 + ru;
        pf[uu] = make_float4(0.f, 0.f, 0.f, 0.f);
        if (h >= 0 && h < HH) {
            const float* p = xb + ((size_t)(2 * c2) * HH + h) * WW + 2 * l;
            float2 va = *(const float2*)p;
            float2 vb = *(const float2*)(p + HWPIX);
            pf[uu] = make_float4(va.x, va.y, vb.x, vb.y);
        }
    }

    for (int ch = 0; ch < NCHUNK; ch++) {
        __syncthreads();   // previous mma phase done reading smem

        // ---- store phase: convert prefetched regs -> smem; pool partials ----
#pragma unroll
        for (int uu = 0; uu < 10; uu++) {
            int u  = wid * 10 + uu;
            int ru = u >> 3, c2 = u & 7;
            float4 v = pf[uu];
            float hax = bfhi(v.x), hay = bfhi(v.y);
            float hbx = bfhi(v.z), hby = bfhi(v.w);
            unsigned hi0 = pkbf(hax, hbx), hi1 = pkbf(hay, hby);
            unsigned lo0 = pkbf(v.x - hax, v.z - hbx);
            unsigned lo1 = pkbf(v.y - hay, v.w - hby);
            int addr = c2 * C2S + ru * ROWW + 2 + 2 * l;
            *(uint2*)&bsm[addr]         = make_uint2(hi0, hi1);
            *(uint2*)&bsm[PLANE + addr] = make_uint2(lo0, lo1);

            if (ru >= 1 && ru <= 8) {   // interior rows -> pool partials
                float sa = v.x + v.y, sb = v.z + v.w;
#pragma unroll
                for (int o = 16; o > 0; o >>= 1) {
                    sa += __shfl_down_sync(0xffffffffu, sa, o);
                    sb += __shfl_down_sync(0xffffffffu, sb, o);
                }
                if (l == 0) {
                    int c0 = ch * CPC + 2 * c2;
                    atomicAdd(&g_pooled[b * CIN + c0], sa);
                    atomicAdd(&g_pooled[b * CIN + c0 + 1], sb);
                }
            }
        }
        __syncthreads();   // tile ready

        // ---- prefetch next chunk (latency hidden under mma phase) ----
        if (ch + 1 < NCHUNK) {
#pragma unroll
            for (int uu = 0; uu < 10; uu++) {
                int u = wid * 10 + uu;
                int ru = u >> 3, c2 = u & 7;
                int h = h0 - 1 + ru;
                pf[uu] = make_float4(0.f, 0.f, 0.f, 0.f);
                if (h >= 0 && h < HH) {
                    const float* p = xb +
                        ((size_t)((ch + 1) * CPC + 2 * c2) * HH + h) * WW + 2 * l;
                    float2 va = *(const float2*)p;
                    float2 vb = *(const float2*)(p + HWPIX);
                    pf[uu] = make_float4(va.x, va.y, vb.x, vb.y);
                }
            }
        }

        // ---- mma phase: 9 taps x 8 pixel-groups x 2 planes; af double-buffered ----
        const int rw = wid + 1;
        uint4 af = g_afrag[(ch * 9) * 32 + l];
#pragma unroll
        for (int tap = 0; tap < 9; tap++) {
            uint4 afn = af;
            if (tap < 8) afn = g_afrag[(ch * 9 + tap + 1) * 32 + l];
            const int dy = tap / 3 - 1, dx = tap % 3 - 1;
            const int base = (rw + dy) * ROWW + dx + 2 + gid;
            const unsigned* bhi = &bsm[tig * C2S + base];
            const unsigned* blo = bhi + PLANE;
#pragma unroll
            for (int g = 0; g < 8; g++) {
                mma16816(acc[g], af, bhi[g * 8], bhi[4 * C2S + g * 8]);
                mma16816(acc[g], af, blo[g * 8], blo[4 * C2S + g * 8]);
            }
            af = afn;
        }
    }

    // ---- epilogue: y[n][px] = hi-row + lo-row accumulators ----
    const int h = h0 + wid;
#pragma unroll
    for (int g = 0; g < 8; g++) {
        int w0 = g * 8 + tig * 2;
        float2 o = make_float2(acc[g][0] + acc[g][2], acc[g][1] + acc[g][3]);
        *(float2*)(g_y + ((size_t)(b * NB + gid) * HH + h) * WW + w0) = o;
    }
}

// -------- kernel 2: attention MLP + softmax, latency-optimized (R16) --------
__global__ __launch_bounds__(256)
void mlp_kernel(const float* __restrict__ w1, const float* __restrict__ b1,
                const float* __restrict__ w2, const float* __restrict__ b2) {
    __shared__ float psm[CIN];
    __shared__ float hs[HID];
    __shared__ float raw[512];
    const int b = blockIdx.x >> 2, q = blockIdx.x & 3;
    const int t = threadIdx.x;
    const int w = t >> 5, l = t & 31;

    psm[t] = g_pooled[b * CIN + t] * (1.f / (float)HWPIX);
    __syncthreads();

#pragma unroll
    for (int i = 0; i < 16; i += 2) {
        float s[2];
#pragma unroll
        for (int rr = 0; rr < 2; rr++) {
            int j = w * 16 + i + rr;
            float4 wa = *(const float4*)(w1 + (size_t)j * CIN + 8 * l);
            float4 wbv = *(const float4*)(w1 + (size_t)j * CIN + 8 * l + 4);
            const float4 pa = *(const float4*)(psm + 8 * l);
            const float4 pb = *(const float4*)(psm + 8 * l + 4);
            s[rr] = wa.x * pa.x + wa.y * pa.y + wa.z * pa.z + wa.w * pa.w
                  + wbv.x * pb.x + wbv.y * pb.y + wbv.z * pb.z + wbv.w * pb.w;
        }
#pragma unroll
        for (int o = 16; o > 0; o >>= 1) {
            s[0] += __shfl_xor_sync(0xffffffffu, s[0], o);
            s[1] += __shfl_xor_sync(0xffffffffu, s[1], o);
        }
        if (l == 0) {
            int j = w * 16 + i;
            hs[j]     = fmaxf(s[0] + b1[j], 0.f);
            hs[j + 1] = fmaxf(s[1] + b1[j + 1], 0.f);
        }
    }
    __syncthreads();

    const float4 hv0 = *(const float4*)(hs + 4 * l);
    const int rbase = q * 512 + w * 64;
#pragma unroll 2
    for (int i = 0; i < 64; i += 4) {
        float s[4];
#pragma unroll
        for (int rr = 0; rr < 4; rr++) {
            int row = rbase + i + rr;
            float4 wv = *(const float4*)(w2 + (size_t)row * HID + 4 * l);
            s[rr] = wv.x * hv0.x + wv.y * hv0.y + wv.z * hv0.z + wv.w * hv0.w;
        }
#pragma unroll
        for (int o = 16; o > 0; o >>= 1) {
#pragma unroll
            for (int rr = 0; rr < 4; rr++)
                s[rr] += __shfl_xor_sync(0xffffffffu, s[rr], o);
        }
        if (l == 0) {
#pragma unroll
            for (int rr = 0; rr < 4; rr++)
                raw[w * 64 + i + rr] = s[rr] + b2[rbase + i + rr];
        }
    }
    __syncthreads();

    if (t < 64) {
        float v[NB];
#pragma unroll
        for (int n = 0; n < NB; n++) v[n] = raw[t * NB + n];
        float m = v[0];
#pragma unroll
        for (int n = 1; n < NB; n++) m = fmaxf(m, v[n]);
        float e[NB], s = 0.f;
#pragma unroll
        for (int n = 0; n < NB; n++) { e[n] = expf(v[n] - m); s += e[n]; }
        float inv = 1.f / s;
        const int o = q * 64 + t;
#pragma unroll
        for (int n = 0; n < NB; n++) g_mix[(b * COUT + o) * NB + n] = e[n] * inv;
    }
}

// -------- kernel 3: out[b,o,p] = sum_n mix[b,o,n] * y[b,n,p] (R16) --------
__global__ __launch_bounds__(256)
void apply_kernel(float* __restrict__ out) {
    __shared__ __align__(16) float ms[64 * NB];
    const int b  = blockIdx.x >> 4;
    const int oq = (blockIdx.x >> 2) & 3;
    const int t  = threadIdx.x;
    const int p0 = (blockIdx.x & 3) * 1024 + t * 4;

    for (int i = t; i < 64 * NB; i += 256)
        ms[i] = g_mix[b * COUT * NB + oq * 64 * NB + i];
    __syncthreads();

    unsigned long long y2[NB][2];
#pragma unroll
    for (int n = 0; n < NB; n++) {
        float4 v = *(const float4*)(g_y + (size_t)(b * NB + n) * HWPIX + p0);
        y2[n][0] = pk2(v.x, v.y);
        y2[n][1] = pk2(v.z, v.w);
    }

    float* ob = out + ((size_t)b * COUT + oq * 64) * HWPIX + p0;
    for (int o = 0; o < 64; o++) {
        const float4 m0 = *(const float4*)(ms + o * NB);
        const float4 m1 = *(const float4*)(ms + o * NB + 4);
        float mv[8] = {m0.x, m0.y, m0.z, m0.w, m1.x, m1.y, m1.z, m1.w};
        unsigned long long a0 = 0ULL, a1 = 0ULL;
#pragma unroll
        for (int n = 0; n < NB; n++) {
            unsigned long long fb = pk2(mv[n], mv[n]);
            a0 = fma2(y2[n][0], fb, a0);
            a1 = fma2(y2[n][1], fb, a1);
        }
        float o0, o1, o2, o3;
        upk2(a0, o0, o1);
        upk2(a1, o2, o3);
        __stcs((float4*)(ob + (size_t)o * HWPIX), make_float4(o0, o1, o2, o3));
    }
}

extern "C" void kernel_launch(void* const* d_in, const int* in_sizes, int n_in,
                              void* d_out, int out_size) {
    const float* x  = (const float*)d_in[0];
    const float* w1 = (const float*)d_in[1];
    const float* b1 = (const float*)d_in[2];
    const float* w2 = (const float*)d_in[3];
    const float* b2 = (const float*)d_in[4];
    const float* bf = (const float*)d_in[5];
    float* out = (float*)d_out;

    zero_kernel<<<(BB * CIN + 255) / 256, 256>>>();
    prep_kernel<<<(NCHUNK * 9 * 32 + 255) / 256, 256>>>(bf);
    conv_pool_kernel<<<BB * 8, 256>>>(x);
    mlp_kernel<<<BB * 4, 256>>>(w1, b1, w2, b2);
    apply_kernel<<<BB * 16, 256>>>(out);
}